// round 13
// baseline (speedup 1.0000x reference)
#include <cuda_runtime.h>
#include <cuda_bf16.h>

#define BATCH 8
#define CH    3
#define TT    16
#define H     512
#define WID   512
#define S     224
#define RMAXF 1024.0f

#define PLANES_PER_B (CH * TT)
#define P 3                         // planes per block-group
#define HWPLANE (H * WID)
#define SSPLANE (S * S)
#define OPLB (SSPLANE * 4)          // out plane stride, bytes

#define NR   10                     // staged source rows (covers 8 out rows + y1)
#define SMW  232                    // staged row stride in floats (16B-aligned)
#define SMW4 (SMW / 4)              // float4s per staged row

// Two-phase block: (1) stage the block's source window (<=10 rows x <=228 cols
// x 3 planes) into smem with coalesced float4 loads -- every source line
// touched once, no gather replays; (2) R10's pair-pixel bilinear, but gathers
// are LDS.64 (29cy) instead of DRAM-latency LDG. Offsets<32 & scale<=1 =>
// y0<=254, window fits, no clamps anywhere.
__global__ __launch_bounds__(256) void crop_prompter_kernel(
    const float* __restrict__ x,
    const int*   __restrict__ cam_views,
    const float* __restrict__ resize,
    const float* __restrict__ yoffs,
    const float* __restrict__ xoffs,
    float*       __restrict__ out)
{
    __shared__ float st[P][NR][SMW];    // 27840 B

    const int group  = blockIdx.z;
    const int plane0 = group * P;
    const int b      = group / (PLANES_PER_B / P);
    const int tx     = threadIdx.x;
    const int ty     = threadIdx.y;

    // Per-camera params
    const int   cam   = __ldg(&cam_views[b]);
    const float r     = floorf(fminf(fmaxf(__ldg(&resize[cam]), (float)H), RMAXF));
    const float scale = (float)H / r;          // in [0.5, 1.0]
    const float yo    = floorf(fminf(fmaxf(__ldg(&yoffs[cam]), 0.0f), r - (float)S));
    const float xo    = floorf(fminf(fmaxf(__ldg(&xoffs[cam]), 0.0f), r - (float)S));

    // Block-common staging origin
    const int ys0 = blockIdx.y * 8;
    const float sy0 = fmaxf((yo + (float)ys0 + 0.5f) * scale - 0.5f, 0.0f);
    const int   ry0 = (int)sy0;                // first staged source row
    const float base  = (xo + 0.5f) * scale - 0.5f;
    const int   cbase = (int)fmaxf(base, 0.0f);
    const int   cg    = cbase & ~3;            // 16B-aligned first staged col

    // ---- Phase 1: stage window (P*NR*SMW4 = 1740 float4) ----
    {
        const float* __restrict__ src = x + (size_t)plane0 * HWPLANE
                                          + (size_t)ry0 * WID + cg;
        const int t = ty * 32 + tx;
        #pragma unroll
        for (int idx = t; idx < P * NR * SMW4; idx += 256) {
            const int k   = idx / (NR * SMW4);
            const int rem = idx % (NR * SMW4);
            const int row = rem / SMW4;
            const int c4  = rem % SMW4;
            const float4 v = *(const float4*)(src + (size_t)k * HWPLANE
                                                  + row * WID + c4 * 4);
            *(float4*)&st[k][row][c4 * 4] = v;
        }
    }
    __syncthreads();

    // ---- Phase 2: compute (one warp per output row) ----
    const int ys = ys0 + ty;
    const float sy = fmaxf((yo + (float)ys + 0.5f) * scale - 0.5f, 0.0f);
    const int   y0 = (int)sy;
    const float wy = sy - (float)y0, onewy = 1.0f - wy;
    const int   yr = y0 - ry0;                 // 0..8 within staged window

    char* __restrict__ obase =
        (char*)(out + (size_t)plane0 * SSPLANE + (size_t)ys * S);

    #pragma unroll
    for (int i = 0; i < 4; ++i) {
        const int j = tx + 32 * i;             // pair index; pixels 2j, 2j+1
        if (j < S / 2) {
            const float rawa = fmaf((float)(2 * j), scale, base);
            const float sxa  = fmaxf(rawa, 0.0f);
            const float sxb  = rawa + scale;   // >= 0.25

            const int   x0a = (int)sxa;
            const int   x0b = (int)sxb;        // == x0a or x0a+1
            const float wxa = sxa - (float)x0a, onewxa = 1.0f - wxa;
            const float wxb = sxb - (float)x0b, onewxb = 1.0f - wxb;

            const int  c0 = x0a & ~1;          // even; cols c0..c0+3 needed
            const int  col = c0 - cg;          // >= 0, col+3 <= SMW-1
            const bool pp = (x0a & 1) != 0;
            const int  q  = (x0a & 1) + (x0b - x0a);  // 0..2
            const bool q1 = (q >= 1), q2 = (q == 2);

            char* oj = obase + (size_t)j * 8;

            #pragma unroll
            for (int k = 0; k < P; ++k) {
                const float2* s0 = (const float2*)&st[k][yr][col];
                const float2* s1 = (const float2*)&st[k][yr + 1][col];
                const float2 u0 = s0[0];
                const float2 u1 = s0[1];
                const float2 v0 = s1[0];
                const float2 v1 = s1[1];

                // y-lerp 4 columns (reference order: y first)
                const float m0 = u0.x * onewy + v0.x * wy;
                const float m1 = u0.y * onewy + v0.y * wy;
                const float m2 = u1.x * onewy + v1.x * wy;
                const float m3 = u1.y * onewy + v1.y * wy;

                const float va_e = m0 * onewxa + m1 * wxa;
                const float va_o = m1 * onewxa + m2 * wxa;
                const float va   = pp ? va_o : va_e;

                float mb0 = q1 ? m1 : m0;  mb0 = q2 ? m2 : mb0;
                float mb1 = q1 ? m2 : m1;  mb1 = q2 ? m3 : mb1;
                const float vb = mb0 * onewxb + mb1 * wxb;

                *(float2*)(oj + k * OPLB) = make_float2(va, vb);
            }
        }
    }
}

extern "C" void kernel_launch(void* const* d_in, const int* in_sizes, int n_in,
                              void* d_out, int out_size)
{
    const float* x    = (const float*)d_in[0];
    const int*   cams = (const int*)  d_in[1];
    const float* rz   = (const float*)d_in[2];
    const float* yo   = (const float*)d_in[3];
    const float* xo   = (const float*)d_in[4];
    float* out = (float*)d_out;

    dim3 block(32, 8, 1);
    dim3 grid(1, S / 8, (BATCH * PLANES_PER_B) / P);
    crop_prompter_kernel<<<grid, block>>>(x, cams, rz, yo, xo, out);
}

// round 14
// speedup vs baseline: 1.2037x; 1.2037x over previous
#include <cuda_runtime.h>
#include <cuda_bf16.h>

#define BATCH 8
#define CH    3
#define TT    16
#define H     512
#define WID   512
#define S     224
#define RMAXF 1024.0f

#define PLANES_PER_B (CH * TT)
#define P 3
#define HWPLANE (H * WID)
#define SSPLANE (S * S)
#define PLB  (HWPLANE * 4)         // plane stride, bytes (LDG imm)
#define ROWB (WID * 4)             // source row stride, bytes
#define OPLB (SSPLANE * 4)         // out plane stride, bytes
#define OROWB (S * 4)              // out row stride, bytes

// 2x2 output tile per lane per plane: adjacent output rows share source rows
// (scale<=1 -> y0 delta in {0,1}), so the tile's footprint is 3 source rows x
// 4 cols = 6 LDG.64 per plane for 4 pixels (was 8). The odd row's y-lerp over
// the 3-row window uses per-warp tent weights (exact bilinear, no selects):
//   t0=max(0,1-fo), t1=1-|fo-1|, t2=max(0,fo-1),  fo = sy_odd - ry in [0,2).
// x path identical to R10 (pair trick, even 8B-aligned base, no clamps).
__global__ __launch_bounds__(256, 4) void crop_prompter_kernel(
    const float* __restrict__ x,
    const int*   __restrict__ cam_views,
    const float* __restrict__ resize,
    const float* __restrict__ yoffs,
    const float* __restrict__ xoffs,
    float*       __restrict__ out)
{
    const int group  = blockIdx.z;
    const int plane0 = group * P;
    const int b      = group / (PLANES_PER_B / P);
    const int tx     = threadIdx.x;
    const int ty     = threadIdx.y;

    const int   cam   = __ldg(&cam_views[b]);
    const float r     = floorf(fminf(fmaxf(__ldg(&resize[cam]), (float)H), RMAXF));
    const float scale = (float)H / r;          // in [0.5, 1.0]
    const float yo    = floorf(fminf(fmaxf(__ldg(&yoffs[cam]), 0.0f), r - (float)S));
    const float xo    = floorf(fminf(fmaxf(__ldg(&xoffs[cam]), 0.0f), r - (float)S));

    // Row pair: output rows 2*rp, 2*rp+1
    const int rp = blockIdx.y * 8 + ty;        // 0..111
    const float sy_e = fmaxf((yo + (float)(2 * rp)     + 0.5f) * scale - 0.5f, 0.0f);
    const float sy_o = fmaxf((yo + (float)(2 * rp + 1) + 0.5f) * scale - 0.5f, 0.0f);
    const int   ry   = (int)sy_e;              // <= 254; window rows ry..ry+2 valid
    const float fe   = sy_e - (float)ry,  one_fe = 1.0f - fe;
    const float fo   = sy_o - (float)ry;       // in [0,2)
    const float to0  = fmaxf(1.0f - fo, 0.0f);
    const float to1  = 1.0f - fabsf(fo - 1.0f);
    const float to2  = fmaxf(fo - 1.0f, 0.0f);

    const char* __restrict__ pbase =
        (const char*)(x + (size_t)plane0 * HWPLANE + (size_t)ry * WID);
    char* __restrict__ obase =
        (char*)(out + (size_t)plane0 * SSPLANE + (size_t)(2 * rp) * S);

    const float base = (xo + 0.5f) * scale - 0.5f;

    #pragma unroll
    for (int i = 0; i < 4; ++i) {
        const int j = tx + 32 * i;             // col-pair index; pixels 2j,2j+1
        if (j < S / 2) {
            const float rawa = fmaf((float)(2 * j), scale, base);
            const float sxa  = fmaxf(rawa, 0.0f);
            const float sxb  = rawa + scale;

            const int   x0a = (int)sxa;
            const int   x0b = (int)sxb;
            const float wxa = sxa - (float)x0a, onewxa = 1.0f - wxa;
            const float wxb = sxb - (float)x0b, onewxb = 1.0f - wxb;

            const int  c0 = x0a & ~1;
            const bool pp = (x0a & 1) != 0;
            const int  q  = (x0a & 1) + (x0b - x0a);
            const bool q1 = (q >= 1), q2 = (q == 2);

            const char* a  = pbase + (size_t)c0 * 4;
            char*       oj = obase + (size_t)j * 8;

            // Batched loads: 18 LDG.64 (3 planes x 3 rows x 2)
            float2 L0[P], L1[P], M0[P], M1[P], N0[P], N1[P];
            #pragma unroll
            for (int k = 0; k < P; ++k) {
                L0[k] = *(const float2*)(a + k * PLB);
                L1[k] = *(const float2*)(a + k * PLB + 8);
                M0[k] = *(const float2*)(a + k * PLB + ROWB);
                M1[k] = *(const float2*)(a + k * PLB + ROWB + 8);
                N0[k] = *(const float2*)(a + k * PLB + 2 * ROWB);
                N1[k] = *(const float2*)(a + k * PLB + 2 * ROWB + 8);
            }

            #pragma unroll
            for (int k = 0; k < P; ++k) {
                // even row y-lerp (rows ry, ry+1)
                const float me0 = L0[k].x * one_fe + M0[k].x * fe;
                const float me1 = L0[k].y * one_fe + M0[k].y * fe;
                const float me2 = L1[k].x * one_fe + M1[k].x * fe;
                const float me3 = L1[k].y * one_fe + M1[k].y * fe;

                // odd row y-lerp via tent weights over rows ry..ry+2
                const float mo0 = L0[k].x * to0 + M0[k].x * to1 + N0[k].x * to2;
                const float mo1 = L0[k].y * to0 + M0[k].y * to1 + N0[k].y * to2;
                const float mo2 = L1[k].x * to0 + M1[k].x * to1 + N1[k].x * to2;
                const float mo3 = L1[k].y * to0 + M1[k].y * to1 + N1[k].y * to2;

                // x-lerp, even row
                {
                    const float va_e = me0 * onewxa + me1 * wxa;
                    const float va_o = me1 * onewxa + me2 * wxa;
                    const float va   = pp ? va_o : va_e;
                    float mb0 = q1 ? me1 : me0;  mb0 = q2 ? me2 : mb0;
                    float mb1 = q1 ? me2 : me1;  mb1 = q2 ? me3 : mb1;
                    const float vb = mb0 * onewxb + mb1 * wxb;
                    *(float2*)(oj + k * OPLB) = make_float2(va, vb);
                }
                // x-lerp, odd row
                {
                    const float va_e = mo0 * onewxa + mo1 * wxa;
                    const float va_o = mo1 * onewxa + mo2 * wxa;
                    const float va   = pp ? va_o : va_e;
                    float mb0 = q1 ? mo1 : mo0;  mb0 = q2 ? mo2 : mb0;
                    float mb1 = q1 ? mo2 : mo1;  mb1 = q2 ? mo3 : mb1;
                    const float vb = mb0 * onewxb + mb1 * wxb;
                    *(float2*)(oj + k * OPLB + OROWB) = make_float2(va, vb);
                }
            }
        }
    }
}

extern "C" void kernel_launch(void* const* d_in, const int* in_sizes, int n_in,
                              void* d_out, int out_size)
{
    const float* x    = (const float*)d_in[0];
    const int*   cams = (const int*)  d_in[1];
    const float* rz   = (const float*)d_in[2];
    const float* yo   = (const float*)d_in[3];
    const float* xo   = (const float*)d_in[4];
    float* out = (float*)d_out;

    dim3 block(32, 8, 1);
    dim3 grid(1, (S / 2) / 8, (BATCH * PLANES_PER_B) / P);
    crop_prompter_kernel<<<grid, block>>>(x, cams, rz, yo, xo, out);
}